// round 9
// baseline (speedup 1.0000x reference)
#include <cuda_runtime.h>
#include <cuda_bf16.h>
#include <math.h>
#include <stdint.h>

// Problem constants
#define N_NODES 50000
#define N_EDGES 800000
#define F_IN    128
#define F_HID   256
#define F_OUT   64

#define GSYNC_BLOCKS 296   // 2 per SM, guaranteed co-resident

// ---------------- scratch (static __device__; no allocation) -----------------
__device__ int      g_deg[N_NODES];
__device__ int      g_off[N_NODES + 1];
__device__ int      g_cur[N_NODES];
__device__ int      g_csr[N_EDGES];
__device__ int      g_bsum[GSYNC_BLOCKS];
__device__ int      g_boff[GSYNC_BLOCKS];
__device__ unsigned g_barc;               // monotonic grid-barrier counter
// Layer-1 A = [agg1 | x] pre-split to bf16 hi/lo, [M][256]
__device__ __nv_bfloat16 g_A1hi[(size_t)N_NODES * 256];
__device__ __nv_bfloat16 g_A1lo[(size_t)N_NODES * 256];
__device__ float g_t[(size_t)N_NODES * F_OUT];   // h @ W_l2
__device__ float g_u[(size_t)N_NODES * F_OUT];   // h @ W_r2
// pre-split / transposed / stacked weights (bf16 hi+lo), [N][K] k-contiguous
__device__ __nv_bfloat16 g_Bt1_hi[256 * 256];
__device__ __nv_bfloat16 g_Bt1_lo[256 * 256];
__device__ __nv_bfloat16 g_Bt2_hi[128 * 256];
__device__ __nv_bfloat16 g_Bt2_lo[128 * 256];

// ---------------- helpers ----------------------------------------------------
__device__ __forceinline__ uint32_t smem_u32(const void* p) {
    uint32_t a;
    asm("{ .reg .u64 t; cvta.to.shared.u64 t, %1; cvt.u32.u64 %0, t; }" : "=r"(a) : "l"(p));
    return a;
}
// 64B-row swizzle (staging buffers)
__device__ __forceinline__ uint32_t sw64(uint32_t off) { return off ^ ((off >> 3) & 0x30); }
// 512B-row swizzle (h buffer): fold row bits [9:12) into bank bits [4:7)
__device__ __forceinline__ uint32_t swh(uint32_t off) { return off ^ ((off >> 5) & 0x70); }

__device__ __forceinline__ uint32_t pack2(__nv_bfloat16 a, __nv_bfloat16 b) {
    return (uint32_t)__bfloat16_as_ushort(a) | ((uint32_t)__bfloat16_as_ushort(b) << 16);
}
__device__ __forceinline__ void split2(float a, float b, uint32_t& hi, uint32_t& lo) {
    __nv_bfloat16 h0 = __float2bfloat16(a), h1 = __float2bfloat16(b);
    __nv_bfloat16 l0 = __float2bfloat16(a - __bfloat162float(h0));
    __nv_bfloat16 l1 = __float2bfloat16(b - __bfloat162float(h1));
    hi = pack2(h0, h1);
    lo = pack2(l0, l1);
}
__device__ __forceinline__ void split4(float4 v, uint2& hi, uint2& lo) {
    split2(v.x, v.y, hi.x, lo.x);
    split2(v.z, v.w, hi.y, lo.y);
}

#define CP_ASYNC16(dst, src, sz) \
    asm volatile("cp.async.cg.shared.global [%0], [%1], 16, %2;" \
                 :: "r"(dst), "l"(src), "r"(sz) : "memory")
#define CP_COMMIT() asm volatile("cp.async.commit_group;" ::: "memory")
#define CP_WAIT(n)  asm volatile("cp.async.wait_group %0;" :: "n"(n) : "memory")

#define LDSM4(r, addr) \
    asm volatile("ldmatrix.sync.aligned.m8n8.x4.shared.b16 {%0,%1,%2,%3}, [%4];" \
                 : "=r"((r)[0]), "=r"((r)[1]), "=r"((r)[2]), "=r"((r)[3]) : "r"(addr))

#define MMA_BF16(d, a, b0, b1) \
    asm volatile("mma.sync.aligned.m16n8k16.row.col.f32.bf16.bf16.f32 " \
                 "{%0,%1,%2,%3}, {%4,%5,%6,%7}, {%8,%9}, {%0,%1,%2,%3};" \
                 : "+f"((d)[0]), "+f"((d)[1]), "+f"((d)[2]), "+f"((d)[3]) \
                 : "r"((a)[0]), "r"((a)[1]), "r"((a)[2]), "r"((a)[3]), "r"(b0), "r"(b1))

// Monotonic-counter grid barrier (counter never reset; wrap unreachable).
__device__ __forceinline__ void grid_sync() {
    __syncthreads();
    if (threadIdx.x == 0) {
        __threadfence();
        unsigned arrive = atomicAdd(&g_barc, 1) + 1;
        unsigned target = ((arrive + GSYNC_BLOCKS - 1) / GSYNC_BLOCKS) * GSYNC_BLOCKS;
        while (atomicAdd(&g_barc, 0) < target) __nanosleep(64);
        __threadfence();
    }
    __syncthreads();
}

// ---------------- CSR build: one persistent kernel ---------------------------
__global__ __launch_bounds__(256)
void csr_coop_kernel(const int* __restrict__ src, const int* __restrict__ dst,
                     int e, int n)
{
    const int G = GSYNC_BLOCKS;
    const int b = blockIdx.x, t = threadIdx.x;
    const int gid = b * 256 + t, gstride = G * 256;
    __shared__ int sh[256];
    __shared__ int sb[GSYNC_BLOCKS];

    for (int i = gid; i < n; i += gstride) g_deg[i] = 0;
    grid_sync();

    int n4 = e >> 2;
    for (int i = gid; i < n4; i += gstride) {
        int4 d = __ldg((const int4*)dst + i);
        atomicAdd(&g_deg[d.x], 1);
        atomicAdd(&g_deg[d.y], 1);
        atomicAdd(&g_deg[d.z], 1);
        atomicAdd(&g_deg[d.w], 1);
    }
    if (gid < (e & 3)) atomicAdd(&g_deg[dst[n4 * 4 + gid]], 1);
    grid_sync();

    int Lb = (n + G - 1) / G;
    int node = b * Lb + t;
    int deg = (t < Lb && node < n) ? g_deg[node] : 0;
    sh[t] = deg;
    __syncthreads();
    for (int s = 1; s < 256; s <<= 1) {
        int v = (t >= s) ? sh[t - s] : 0;
        __syncthreads();
        sh[t] += v;
        __syncthreads();
    }
    int ex = sh[t] - deg;
    if (t == 255) g_bsum[b] = sh[255];
    grid_sync();

    if (b == 0) {
        for (int i = t; i < G; i += 256) sb[i] = g_bsum[i];
        __syncthreads();
        for (int i = t; i < G; i += 256) {
            int acc = 0;
            for (int k = 0; k < i; k++) acc += sb[k];
            g_boff[i] = acc;
        }
    }
    grid_sync();

    int boff = g_boff[b];
    if (t < Lb && node < n) {
        g_off[node] = boff + ex;
        g_cur[node] = boff + ex;
    }
    if (b == G - 1 && t == 0) g_off[n] = g_boff[G - 1] + g_bsum[G - 1];
    grid_sync();

    for (int i = gid; i < n4; i += gstride) {
        int4 d = __ldg((const int4*)dst + i);
        int4 s = __ldg((const int4*)src + i);
        g_csr[atomicAdd(&g_cur[d.x], 1)] = s.x;
        g_csr[atomicAdd(&g_cur[d.y], 1)] = s.y;
        g_csr[atomicAdd(&g_cur[d.z], 1)] = s.z;
        g_csr[atomicAdd(&g_cur[d.w], 1)] = s.w;
    }
    if (gid < (e & 3)) {
        int j = n4 * 4 + gid;
        g_csr[atomicAdd(&g_cur[dst[j]], 1)] = src[j];
    }
}

// ---------------- layer-1 aggregation + x convert (fused, warp per node) -----
__global__ void agg128_kernel(const float* __restrict__ x) {
    int w = (blockIdx.x * blockDim.x + threadIdx.x) >> 5;
    int lane = threadIdx.x & 31;
    if (w >= N_NODES) return;
    int s = g_off[w], e = g_off[w + 1];
    float4 a0 = make_float4(0.f, 0.f, 0.f, 0.f), a1 = a0, a2 = a0, a3 = a0;
    int i = s;
    for (; i + 4 <= e; i += 4) {
        int s0 = g_csr[i], s1 = g_csr[i + 1], s2 = g_csr[i + 2], s3 = g_csr[i + 3];
        float4 v0 = __ldg(((const float4*)(x + (size_t)s0 * F_IN)) + lane);
        float4 v1 = __ldg(((const float4*)(x + (size_t)s1 * F_IN)) + lane);
        float4 v2 = __ldg(((const float4*)(x + (size_t)s2 * F_IN)) + lane);
        float4 v3 = __ldg(((const float4*)(x + (size_t)s3 * F_IN)) + lane);
        a0.x += v0.x; a0.y += v0.y; a0.z += v0.z; a0.w += v0.w;
        a1.x += v1.x; a1.y += v1.y; a1.z += v1.z; a1.w += v1.w;
        a2.x += v2.x; a2.y += v2.y; a2.z += v2.z; a2.w += v2.w;
        a3.x += v3.x; a3.y += v3.y; a3.z += v3.z; a3.w += v3.w;
    }
    for (; i < e; i++) {
        int sn = g_csr[i];
        float4 v = __ldg(((const float4*)(x + (size_t)sn * F_IN)) + lane);
        a0.x += v.x; a0.y += v.y; a0.z += v.z; a0.w += v.w;
    }
    float4 acc;
    acc.x = (a0.x + a1.x) + (a2.x + a3.x);
    acc.y = (a0.y + a1.y) + (a2.y + a3.y);
    acc.z = (a0.z + a1.z) + (a2.z + a3.z);
    acc.w = (a0.w + a1.w) + (a2.w + a3.w);
    float inv = (e > s) ? 1.0f / (float)(e - s) : 0.0f;
    acc.x *= inv; acc.y *= inv; acc.z *= inv; acc.w *= inv;
    uint2 hi, lo;
    split4(acc, hi, lo);
    *(uint2*)(g_A1hi + (size_t)w * 256 + lane * 4) = hi;
    *(uint2*)(g_A1lo + (size_t)w * 256 + lane * 4) = lo;
    float4 xv = __ldg(((const float4*)(x + (size_t)w * F_IN)) + lane);
    split4(xv, hi, lo);
    *(uint2*)(g_A1hi + (size_t)w * 256 + 128 + lane * 4) = hi;
    *(uint2*)(g_A1lo + (size_t)w * 256 + 128 + lane * 4) = lo;
}

// layer 2: mean of t fused with sigmoid epilogue
__global__ void agg64_final_kernel(const float* __restrict__ b2, float* __restrict__ out) {
    int w = (blockIdx.x * blockDim.x + threadIdx.x) >> 5;
    int lane = threadIdx.x & 31;
    if (w >= N_NODES) return;
    int s = g_off[w], e = g_off[w + 1];
    float2 a0 = make_float2(0.f, 0.f), a1 = a0, a2 = a0, a3 = a0;
    int i = s;
    for (; i + 4 <= e; i += 4) {
        int s0 = g_csr[i], s1 = g_csr[i + 1], s2 = g_csr[i + 2], s3 = g_csr[i + 3];
        float2 v0 = __ldg(((const float2*)(g_t + (size_t)s0 * F_OUT)) + lane);
        float2 v1 = __ldg(((const float2*)(g_t + (size_t)s1 * F_OUT)) + lane);
        float2 v2 = __ldg(((const float2*)(g_t + (size_t)s2 * F_OUT)) + lane);
        float2 v3 = __ldg(((const float2*)(g_t + (size_t)s3 * F_OUT)) + lane);
        a0.x += v0.x; a0.y += v0.y;
        a1.x += v1.x; a1.y += v1.y;
        a2.x += v2.x; a2.y += v2.y;
        a3.x += v3.x; a3.y += v3.y;
    }
    for (; i < e; i++) {
        int sn = g_csr[i];
        float2 v = __ldg(((const float2*)(g_t + (size_t)sn * F_OUT)) + lane);
        a0.x += v.x; a0.y += v.y;
    }
    float2 acc;
    acc.x = (a0.x + a1.x) + (a2.x + a3.x);
    acc.y = (a0.y + a1.y) + (a2.y + a3.y);
    float inv = (e > s) ? 1.0f / (float)(e - s) : 0.0f;
    float2 u = *(const float2*)(g_u + (size_t)w * F_OUT + lane * 2);
    float bx = __ldg(&b2[lane * 2]);
    float by = __ldg(&b2[lane * 2 + 1]);
    float vx = acc.x * inv + u.x + bx;
    float vy = acc.y * inv + u.y + by;
    float2 o;
    o.x = 1.f / (1.f + __expf(-vx));
    o.y = 1.f / (1.f + __expf(-vy));
    *(float2*)(out + (size_t)w * F_OUT + lane * 2) = o;
}

// ---------------- weight prep: transpose + stack + bf16-split (fused) --------
__global__ void prep_kernel(const float* __restrict__ W_l1, const float* __restrict__ W_r1,
                            const float* __restrict__ W_l2, const float* __restrict__ W_r2) {
    int i = blockIdx.x * blockDim.x + threadIdx.x;
    if (i < 256 * 256) {
        int n = i >> 8, k = i & 255;
        float w = (k < 128) ? W_l1[(size_t)k * 256 + n] : W_r1[(size_t)(k - 128) * 256 + n];
        __nv_bfloat16 hi = __float2bfloat16(w);
        __nv_bfloat16 lo = __float2bfloat16(w - __bfloat162float(hi));
        g_Bt1_hi[i] = hi;
        g_Bt1_lo[i] = lo;
    } else {
        int j = i - 256 * 256;
        if (j >= 128 * 256) return;
        int n = j >> 8, k = j & 255;
        float w = (n < 64) ? W_l2[(size_t)k * 64 + n] : W_r2[(size_t)k * 64 + (n - 64)];
        __nv_bfloat16 hi = __float2bfloat16(w);
        __nv_bfloat16 lo = __float2bfloat16(w - __bfloat162float(hi));
        g_Bt2_hi[j] = hi;
        g_Bt2_lo[j] = lo;
    }
}

// ---------------- FUSED two-layer GEMM ---------------------------------------
// Phase A: h[128,256] = relu(A1[rb:,256] @ Bt1[256,256]^T + b1)  -> smem (bf16 hi/lo)
// Phase B: [t|u][128,128] = h @ Bt2[128,256]^T                   -> global fp32
// 512 threads / 16 warps, 3-term bf16 split throughout, K-chunks of 32,
// double-buffered staging; h never touches global memory.
// Staging buffer (48KB x2): Ahi 8K | Alo 8K | Bhi 16K | Blo 16K
#define SM_BUFSZ  49152
#define SM_AHI    0
#define SM_ALO    8192
#define SM_BHI    16384
#define SM_BLO    32768
#define SM_H      98304          // h_hi 64K here, h_lo 64K at +65536
#define SM_HLO    65536
#define SMEM_FUSED 229376        // 224 KB

__global__ __launch_bounds__(512, 1)
void gemm_fused_kernel(const __nv_bfloat16* __restrict__ Ahi, const __nv_bfloat16* __restrict__ Alo,
                       const __nv_bfloat16* __restrict__ B1hi, const __nv_bfloat16* __restrict__ B1lo,
                       const __nv_bfloat16* __restrict__ B2hi, const __nv_bfloat16* __restrict__ B2lo,
                       const float* __restrict__ bias1,
                       float* __restrict__ t_out, float* __restrict__ u_out, int M)
{
    extern __shared__ __align__(128) char sm[];
    const uint32_t sb = smem_u32(sm);
    const int tid  = threadIdx.x;
    const int wid  = tid >> 5;
    const int lane = tid & 31;
    const int rowBase = blockIdx.x * 128;

    const int t = lane >> 3, rIn = lane & 7;
    const int rowAdd = rIn + (t & 1) * 8;
    const int kAdd = (t >> 1) * 16;      // bytes
    const int g = lane >> 2, cp2 = (lane & 3) * 2;

    // ======================= PHASE A =======================
    // warp grid 4(M) x 4(N), warp tile 32x64 over [128 x 256]
    const int wmA = (wid & 3) * 32;
    const int wnA = (wid >> 2) * 64;

    float acc[2][8][4];
#pragma unroll
    for (int a = 0; a < 2; a++)
#pragma unroll
        for (int b = 0; b < 8; b++)
#pragma unroll
            for (int c = 0; c < 4; c++) acc[a][b][c] = 0.f;

    auto issueA = [&](int c, int buf) {
        uint32_t base = sb + buf * SM_BUFSZ;
        {   // A: 128 rows x 64B (hi+lo)
            int r = tid >> 2, j = tid & 3;
            uint32_t off = sw64((uint32_t)(r * 64 + j * 16));
            int arow = rowBase + r;
            int asz = (arow < M) ? 16 : 0;
            size_t aidx = (size_t)min(arow, M - 1) * 256 + c * 32 + j * 8;
            CP_ASYNC16(base + SM_AHI + off, (const char*)(Ahi + aidx), asz);
            CP_ASYNC16(base + SM_ALO + off, (const char*)(Alo + aidx), asz);
        }
#pragma unroll
        for (int i = tid; i < 1024; i += 512) {   // B: 256 rows x 64B (hi+lo)
            int r = i >> 2, j = i & 3;
            uint32_t off = sw64((uint32_t)(r * 64 + j * 16));
            size_t bidx = (size_t)r * 256 + c * 32 + j * 8;
            CP_ASYNC16(base + SM_BHI + off, (const char*)(B1hi + bidx), 16);
            CP_ASYNC16(base + SM_BLO + off, (const char*)(B1lo + bidx), 16);
        }
        CP_COMMIT();
    };

    issueA(0, 0);
#pragma unroll 1
    for (int c = 0; c < 8; c++) {
        if (c < 7) { issueA(c + 1, (c + 1) & 1); CP_WAIT(1); }
        else       { CP_WAIT(0); }
        __syncthreads();
        uint32_t base = sb + (c & 1) * SM_BUFSZ;
#pragma unroll
        for (int ks = 0; ks < 2; ks++) {
            int kB = ks * 32 + kAdd;
            uint32_t ah[2][4], al[2][4];
#pragma unroll
            for (int mt = 0; mt < 2; mt++) {
                uint32_t ad = base + SM_AHI + sw64((uint32_t)((wmA + mt * 16 + rowAdd) * 64 + kB));
                LDSM4(ah[mt], ad);
                LDSM4(al[mt], ad + (SM_ALO - SM_AHI));
            }
#pragma unroll
            for (int n4 = 0; n4 < 4; n4++) {
                uint32_t bh[4], bl[4];
                uint32_t bd = base + SM_BHI + sw64((uint32_t)((wnA + n4 * 16 + rowAdd) * 64 + kB));
                LDSM4(bh, bd);
                LDSM4(bl, bd + (SM_BLO - SM_BHI));
#pragma unroll
                for (int hf = 0; hf < 2; hf++) {
                    int nt = n4 * 2 + hf;
                    MMA_BF16(acc[0][nt], ah[0], bh[hf], bh[hf + 2]);
                    MMA_BF16(acc[1][nt], ah[1], bh[hf], bh[hf + 2]);
                    MMA_BF16(acc[0][nt], ah[0], bl[hf], bl[hf + 2]);
                    MMA_BF16(acc[1][nt], ah[1], bl[hf], bl[hf + 2]);
                    MMA_BF16(acc[0][nt], al[0], bh[hf], bh[hf + 2]);
                    MMA_BF16(acc[1][nt], al[1], bh[hf], bh[hf + 2]);
                }
            }
        }
        __syncthreads();
    }

    // start first phase-B load (overlaps epilogue A); buf0 is free.
    {
        int r = tid >> 2, j = tid & 3;        // B2: 128 rows x 64B
        uint32_t off = sw64((uint32_t)(r * 64 + j * 16));
        size_t bidx = (size_t)r * 256 + 0 * 32 + j * 8;
        CP_ASYNC16(sb + SM_BHI + off, (const char*)(B2hi + bidx), 16);
        CP_ASYNC16(sb + SM_BLO + off, (const char*)(B2lo + bidx), 16);
        CP_COMMIT();
    }

    // ---- epilogue A: bias + relu + bf16 split -> h in smem ----
#pragma unroll
    for (int mt = 0; mt < 2; mt++)
#pragma unroll
        for (int nt = 0; nt < 8; nt++) {
            int r0 = wmA + mt * 16 + g;
            int cc = wnA + nt * 8 + cp2;
            float bA = __ldg(&bias1[cc]);
            float bB = __ldg(&bias1[cc + 1]);
            float v0 = fmaxf(acc[mt][nt][0] + bA, 0.f);
            float v1 = fmaxf(acc[mt][nt][1] + bB, 0.f);
            float v2 = fmaxf(acc[mt][nt][2] + bA, 0.f);
            float v3 = fmaxf(acc[mt][nt][3] + bB, 0.f);
            uint32_t hi, lo;
            split2(v0, v1, hi, lo);
            uint32_t off = swh((uint32_t)(r0 * 512 + cc * 2));
            *(uint32_t*)(sm + SM_H + off) = hi;
            *(uint32_t*)(sm + SM_H + SM_HLO + off) = lo;
            split2(v2, v3, hi, lo);
            off = swh((uint32_t)((r0 + 8) * 512 + cc * 2));
            *(uint32_t*)(sm + SM_H + off) = hi;
            *(uint32_t*)(sm + SM_H + SM_HLO + off) = lo;
        }

    // ======================= PHASE B =======================
    // warp grid 4(M) x 4(N), warp tile 32x32 over [128 x 128]
    const int wmB = (wid & 3) * 32;
    const int wnB = (wid >> 2) * 32;

    float acc2[2][4][4];
#pragma unroll
    for (int a = 0; a < 2; a++)
#pragma unroll
        for (int b = 0; b < 4; b++)
#pragma unroll
            for (int c = 0; c < 4; c++) acc2[a][b][c] = 0.f;

    auto issueB = [&](int c, int buf) {
        uint32_t base = sb + buf * SM_BUFSZ;
        int r = tid >> 2, j = tid & 3;        // B2: 128 rows x 64B
        uint32_t off = sw64((uint32_t)(r * 64 + j * 16));
        size_t bidx = (size_t)r * 256 + c * 32 + j * 8;
        CP_ASYNC16(base + SM_BHI + off, (const char*)(B2hi + bidx), 16);
        CP_ASYNC16(base + SM_BLO + off, (const char*)(B2lo + bidx), 16);
        CP_COMMIT();
    };

#pragma unroll 1
    for (int c = 0; c < 8; c++) {
        if (c < 7) { issueB(c + 1, (c + 1) & 1); CP_WAIT(1); }
        else       { CP_WAIT(0); }
        __syncthreads();   // first iteration also publishes epilogue-A h writes
        uint32_t base = sb + (c & 1) * SM_BUFSZ;
#pragma unroll
        for (int ks = 0; ks < 2; ks++) {
            int kB = ks * 32 + kAdd;
            uint32_t ah[2][4], al[2][4];
#pragma unroll
            for (int mt = 0; mt < 2; mt++) {
                uint32_t ad = sb + SM_H + swh((uint32_t)((wmB + mt * 16 + rowAdd) * 512 + c * 64 + kB));
                LDSM4(ah[mt], ad);
                LDSM4(al[mt], ad + SM_HLO);
            }
#pragma unroll
            for (int n4 = 0; n4 < 2; n4++) {
                uint32_t bh[4], bl[4];
                uint32_t bd = base + SM_BHI + sw64((uint32_t)((wnB + n4 * 16 + rowAdd) * 64 + kB));
                LDSM4(bh, bd);
                LDSM4(bl, bd + (SM_BLO - SM_BHI));
#pragma unroll
                for (int hf = 0; hf < 2; hf++) {
                    int nt = n4 * 2 + hf;
                    MMA_BF16(acc2[0][nt], ah[0], bh[hf], bh[hf + 2]);
                    MMA_BF16(acc2[1][nt], ah[1], bh[hf], bh[hf + 2]);
                    MMA_BF16(acc2[0][nt], ah[0], bl[hf], bl[hf + 2]);
                    MMA_BF16(acc2[1][nt], ah[1], bl[hf], bl[hf + 2]);
                    MMA_BF16(acc2[0][nt], al[0], bh[hf], bh[hf + 2]);
                    MMA_BF16(acc2[1][nt], al[1], bh[hf], bh[hf + 2]);
                }
            }
        }
        __syncthreads();
    }

    // ---- epilogue B: stage through smem (h area is dead), coalesced stores --
    float* sep = (float*)(sm + SM_H);   // 128 x 132 fp32 = 67584 B
#pragma unroll
    for (int mt = 0; mt < 2; mt++)
#pragma unroll
        for (int nt = 0; nt < 4; nt++) {
            int r0 = wmB + mt * 16 + g;
            int cc = wnB + nt * 8 + cp2;
            sep[r0 * 132 + cc]           = acc2[mt][nt][0];
            sep[r0 * 132 + cc + 1]       = acc2[mt][nt][1];
            sep[(r0 + 8) * 132 + cc]     = acc2[mt][nt][2];
            sep[(r0 + 8) * 132 + cc + 1] = acc2[mt][nt][3];
        }
    __syncthreads();
#pragma unroll 1
    for (int i = tid; i < 128 * 32; i += 512) {
        int r = i >> 5, c4 = (i & 31) * 4;
        int row = rowBase + r;
        if (row < M) {
            float4 v = *(const float4*)&sep[r * 132 + c4];
            if (c4 < 64) *(float4*)(t_out + (size_t)row * 64 + c4) = v;
            else         *(float4*)(u_out + (size_t)row * 64 + c4 - 64) = v;
        }
    }
}

// ---------------- launch -----------------------------------------------------
extern "C" void kernel_launch(void* const* d_in, const int* in_sizes, int n_in,
                              void* d_out, int out_size)
{
    const float* x    = (const float*)d_in[0];
    const int*   ei   = (const int*)  d_in[1];
    const float* W_l1 = (const float*)d_in[2];
    const float* W_r1 = (const float*)d_in[3];
    const float* b1   = (const float*)d_in[4];
    const float* W_l2 = (const float*)d_in[5];
    const float* W_r2 = (const float*)d_in[6];
    const float* b2   = (const float*)d_in[7];
    float*       out  = (float*)d_out;

    int n = in_sizes[0] / F_IN;
    int e = in_sizes[1] / 2;
    const int* srcp = ei;
    const int* dstp = ei + e;

    __nv_bfloat16 *a1h, *a1l, *bt1h, *bt1l, *bt2h, *bt2l;
    float *t_p, *u_p;
    cudaGetSymbolAddress((void**)&a1h,  g_A1hi);
    cudaGetSymbolAddress((void**)&a1l,  g_A1lo);
    cudaGetSymbolAddress((void**)&bt1h, g_Bt1_hi);
    cudaGetSymbolAddress((void**)&bt1l, g_Bt1_lo);
    cudaGetSymbolAddress((void**)&bt2h, g_Bt2_hi);
    cudaGetSymbolAddress((void**)&bt2l, g_Bt2_lo);
    cudaGetSymbolAddress((void**)&t_p,  g_t);
    cudaGetSymbolAddress((void**)&u_p,  g_u);

    cudaFuncSetAttribute(gemm_fused_kernel,
                         cudaFuncAttributeMaxDynamicSharedMemorySize, SMEM_FUSED);

    int mtiles = (n + 127) / 128;

    // launch index 3 (fused gemm) is the one ncu profiles.
    csr_coop_kernel<<<GSYNC_BLOCKS, 256>>>(srcp, dstp, e, n);            // 0
    prep_kernel<<<(256 * 256 + 128 * 256 + 255) / 256, 256>>>(W_l1, W_r1, W_l2, W_r2); // 1
    agg128_kernel<<<(n * 32 + 255) / 256, 256>>>(x);                     // 2
    gemm_fused_kernel<<<mtiles, 512, SMEM_FUSED>>>(a1h, a1l, bt1h, bt1l, bt2h, bt2l,
                                                   b1, t_p, u_p, n);     // 3 (profiled)
    agg64_final_kernel<<<(n * 32 + 255) / 256, 256>>>(b2, out);          // 4
}